// round 5
// baseline (speedup 1.0000x reference)
#include <cuda_runtime.h>
#include <cuda_bf16.h>
#include <cstdint>

#define B_ 128
#define T_ 500
#define D_ 700
#define H_ 512
#define O_ 20
#define KC 2112      // packed split-K: [hi(700) | hi(700) | lo(700) | pad(12)]
#define NS 66        // K stages of 32 bf16 (64 bytes)
#define RS 80        // smem row stride bytes (64 data + 16 pad -> conflict-free ldmatrix)
#define SBUF (128 * RS)

// ---------------- scratch (static device globals: no allocation allowed) ----------------
__device__ __nv_bfloat16 g_xc[(size_t)T_ * B_ * KC];   // 270 MB  [t][b][k]
__device__ __nv_bfloat16 g_wc[(size_t)H_ * KC];        // [h][k]  = [Whi | Wlo | Whi | 0]
__device__ float         g_cur1[(size_t)T_ * B_ * H_]; // 131 MB  [t][b][h]
__device__ float         g_W2T[H_ * H_];               // W2 transposed: [h][g]
__device__ unsigned      g_mask[(size_t)B_ * T_ * 16]; // spike bitmasks, 16 words/(b,t)
__device__ float         g_S2[B_ * H_];                // sum over t of s2

// ---------------- helpers ----------------
__device__ __forceinline__ uint32_t smem_u32(const void* p) {
    uint32_t a;
    asm("{ .reg .u64 t; cvta.to.shared.u64 t, %1; cvt.u32.u64 %0, t; }" : "=r"(a) : "l"(p));
    return a;
}
__device__ __forceinline__ void cp16(uint32_t s, const void* g) {
    asm volatile("cp.async.cg.shared.global [%0], [%1], 16;" :: "r"(s), "l"(g));
}
__device__ __forceinline__ void ldsm4(uint32_t& r0, uint32_t& r1, uint32_t& r2,
                                      uint32_t& r3, uint32_t addr) {
    asm volatile("ldmatrix.sync.aligned.m8n8.x4.shared.b16 {%0,%1,%2,%3}, [%4];"
                 : "=r"(r0), "=r"(r1), "=r"(r2), "=r"(r3) : "r"(addr));
}
__device__ __forceinline__ void mma16816(float* c, const uint32_t* a, const uint32_t* b) {
    asm volatile(
        "mma.sync.aligned.m16n8k16.row.col.f32.bf16.bf16.f32 "
        "{%0,%1,%2,%3}, {%4,%5,%6,%7}, {%8,%9}, {%0,%1,%2,%3};"
        : "+f"(c[0]), "+f"(c[1]), "+f"(c[2]), "+f"(c[3])
        : "r"(a[0]), "r"(a[1]), "r"(a[2]), "r"(a[3]), "r"(b[0]), "r"(b[1]));
}

// ---------------- prep: fp32 -> double-bf16 split, packed K layout ----------------
__global__ void prep_x(const float* __restrict__ x) {
    const int bt = blockIdx.x;             // b*T_ + t  (x is [B][T][D])
    const int b = bt / T_, t = bt % T_;
    const float* xr = x + (size_t)bt * D_;
    __nv_bfloat16* o = g_xc + ((size_t)t * B_ + b) * KC;
    for (int d = threadIdx.x; d < D_; d += 256) {
        float val = xr[d];
        __nv_bfloat16 hi = __float2bfloat16(val);
        __nv_bfloat16 lo = __float2bfloat16(val - __bfloat162float(hi));
        o[d] = hi; o[D_ + d] = hi; o[2 * D_ + d] = lo;
    }
    if (threadIdx.x < KC - 3 * D_) o[3 * D_ + threadIdx.x] = __float2bfloat16(0.f);
}
__global__ void prep_w(const float* __restrict__ W1) {
    const int h = blockIdx.x;
    const float* wr = W1 + (size_t)h * D_;
    __nv_bfloat16* o = g_wc + (size_t)h * KC;
    for (int d = threadIdx.x; d < D_; d += 256) {
        float val = wr[d];
        __nv_bfloat16 hi = __float2bfloat16(val);
        __nv_bfloat16 lo = __float2bfloat16(val - __bfloat162float(hi));
        o[d] = hi; o[D_ + d] = lo; o[2 * D_ + d] = hi;   // pairs with [hi|hi|lo] of x
    }
    if (threadIdx.x < KC - 3 * D_) o[3 * D_ + threadIdx.x] = __float2bfloat16(0.f);
}
__global__ void transpose_w2(const float* __restrict__ W2) {
    int i = blockIdx.x * blockDim.x + threadIdx.x;
    if (i < H_ * H_) {
        int h = i / H_, g = i % H_;
        g_W2T[i] = W2[g * H_ + h];
    }
}

// ---------------- GEMM1 via mma.sync: cur1[t][b][h] = xc[t,b,:].wc[h,:] + b1[h] -------
// grid (4 h-tiles, 500 t), 256 threads. CTA tile M=128(b) x N=128(h), K=2112 bf16.
// 8 warps as 2(m)x4(n), each 64x32 via m16n8k16. cp.async double-buffered K stages of 32.
__global__ __launch_bounds__(256, 2) void gemm1_mma(const float* __restrict__ b1) {
    __shared__ __align__(128) char sA[2 * SBUF];
    __shared__ __align__(128) char sB[2 * SBUF];
    const int tid = threadIdx.x, lane = tid & 31, wid = tid >> 5;
    const int t = blockIdx.y, hbase = blockIdx.x * 128;
    const int wm = wid >> 2, wn = wid & 3;    // warp tile: rows wm*64, cols wn*32

    const char* gA = (const char*)g_xc + (size_t)t * B_ * KC * 2;
    const char* gB = (const char*)g_wc + (size_t)hbase * KC * 2;
    const uint32_t sAu = smem_u32(sA), sBu = smem_u32(sB);

    // stage loader: thread -> row tid>>1, chunks (tid&1)*2, +1
    const int lrow = tid >> 1;
    const int lc = (tid & 1) * 32;            // byte offset of first 16B chunk
    const size_t grow = (size_t)lrow * (KC * 2);

    // ldmatrix lane addressing
    const int arow = lane & 15;
    const int acol = (lane >> 4) * 16;
    const int brow = (lane & 7) + ((lane & 16) ? 8 : 0);
    const int bcol = (lane & 8) ? 16 : 0;

    float acc[4][4][4];
#pragma unroll
    for (int i = 0; i < 4; i++)
#pragma unroll
        for (int j = 0; j < 4; j++)
#pragma unroll
            for (int q = 0; q < 4; q++) acc[i][j][q] = 0.f;

#define LOADSTAGE(s, buf)                                                       \
    do {                                                                        \
        const char* ga = gA + grow + (s) * 64 + lc;                             \
        const char* gb = gB + grow + (s) * 64 + lc;                             \
        uint32_t da = sAu + (buf) * SBUF + lrow * RS + lc;                      \
        uint32_t db = sBu + (buf) * SBUF + lrow * RS + lc;                      \
        cp16(da, ga); cp16(da + 16, ga + 16);                                   \
        cp16(db, gb); cp16(db + 16, gb + 16);                                   \
    } while (0)

    LOADSTAGE(0, 0);
    asm volatile("cp.async.commit_group;");

    for (int s = 0; s < NS; s++) {
        if (s + 1 < NS) {
            LOADSTAGE(s + 1, (s + 1) & 1);
            asm volatile("cp.async.commit_group;");
            asm volatile("cp.async.wait_group 1;");
        } else {
            asm volatile("cp.async.wait_group 0;");
        }
        __syncthreads();
        const int buf = s & 1;
        const uint32_t abase = sAu + buf * SBUF;
        const uint32_t bbase = sBu + buf * SBUF;
#pragma unroll
        for (int ks = 0; ks < 2; ks++) {
            uint32_t a[4][4], bf[4][2];
#pragma unroll
            for (int i = 0; i < 4; i++)
                ldsm4(a[i][0], a[i][1], a[i][2], a[i][3],
                      abase + (wm * 64 + i * 16 + arow) * RS + acol + ks * 32);
#pragma unroll
            for (int j = 0; j < 2; j++)
                ldsm4(bf[2 * j][0], bf[2 * j][1], bf[2 * j + 1][0], bf[2 * j + 1][1],
                      bbase + (wn * 32 + j * 16 + brow) * RS + bcol + ks * 32);
#pragma unroll
            for (int i = 0; i < 4; i++)
#pragma unroll
                for (int j = 0; j < 4; j++) mma16816(acc[i][j], a[i], bf[j]);
        }
        __syncthreads();
    }

    // epilogue: acc tile (i,j): rows wm*64+i*16 + {lane>>2, +8}, cols wn*32+j*8+(lane&3)*2
    const int r0 = wm * 64 + (lane >> 2);
    const int cb = wn * 32 + (lane & 3) * 2;
#pragma unroll
    for (int j = 0; j < 4; j++) {
        const int col = hbase + cb + j * 8;
        const float2 bl = *(const float2*)(b1 + col);
#pragma unroll
        for (int i = 0; i < 4; i++) {
            const int rb = r0 + i * 16;
            float* p0 = g_cur1 + ((size_t)(t * B_ + rb)) * H_ + col;
            float* p1 = g_cur1 + ((size_t)(t * B_ + rb + 8)) * H_ + col;
            *(float2*)p0 = make_float2(acc[i][j][0] + bl.x, acc[i][j][1] + bl.y);
            *(float2*)p1 = make_float2(acc[i][j][2] + bl.x, acc[i][j][3] + bl.y);
        }
    }
}

// ---------------- scan1: barrier-free LIF, emits spike bitmasks ----------------
// grid (4 h-quarters, 128 b), 128 threads. One ballot word per warp per t.
__global__ __launch_bounds__(128) void scan1_kernel() {
    const int hq = blockIdx.x, b = blockIdx.y;
    const int tid = threadIdx.x, lane = tid & 31, w = tid >> 5;
    const float* cp = g_cur1 + (size_t)b * H_ + hq * 128 + tid;
    unsigned* mout = g_mask + ((size_t)b * T_) * 16 + hq * 4 + w;
    float v = 0.f;
    for (int t0 = 0; t0 < T_; t0 += 10) {
        float I[10];
#pragma unroll
        for (int u = 0; u < 10; u++)
            I[u] = cp[(size_t)(t0 + u) * (B_ * H_)];
#pragma unroll
        for (int u = 0; u < 10; u++) {
            v += (I[u] - v) * 0.5f;
            bool s = (v >= 1.0f);
            unsigned m = __ballot_sync(0xffffffffu, s);
            if (s) v = 0.f;
            if (lane == 0) mout[(size_t)(t0 + u) * 16] = m;
        }
    }
}

// ---------------- layer2: mask-driven sparse GEMM2 + LIF scan2 + time-sum ----------
// grid (4 g-quarters, 128 b), 128 threads; thread = one g. Masks shfl-broadcast.
__global__ __launch_bounds__(128) void layer2_kernel(const float* __restrict__ b2) {
    const int b = blockIdx.y;
    const int g = blockIdx.x * 128 + threadIdx.x;
    const int lane = threadIdx.x & 31;
    const float* wcol = g_W2T + g;                 // W2T[h*512 + g], coalesced over g
    const unsigned* mp = g_mask + (size_t)b * T_ * 16;
    const float bb = b2[g];
    float v = 0.f, cnt = 0.f;
    unsigned myw = (lane < 16) ? mp[lane] : 0u;
    for (int t = 0; t < T_; t++) {
        unsigned nxt = 0u;
        if (t + 1 < T_ && lane < 16) nxt = mp[(size_t)(t + 1) * 16 + lane];
        float c[4] = {0.f, 0.f, 0.f, 0.f};
#pragma unroll
        for (int wg = 0; wg < 4; wg++) {
#pragma unroll
            for (int ww = 0; ww < 4; ww++) {
                const int wi = wg * 4 + ww;
                unsigned m = __shfl_sync(0xffffffffu, myw, wi);
                while (m) {
                    int h = wi * 32 + (__ffs(m) - 1);
                    c[wg] += wcol[h << 9];
                    m &= m - 1u;
                }
            }
        }
        float cur = bb + ((c[0] + c[1]) + (c[2] + c[3]));
        v += (cur - v) * 0.5f;
        if (v >= 1.0f) { v = 0.f; cnt += 1.f; }
        myw = nxt;
    }
    g_S2[b * H_ + g] = cnt;
}

// ---------------- final: out[b,o] = 500*b3[o] + sum_h S2[b,h] * W3[o,h] ----------------
__global__ void final_kernel(const float* __restrict__ W3, const float* __restrict__ b3,
                             float* __restrict__ out) {
    __shared__ float sW3[O_ * H_];
    __shared__ float part[4 * O_];
    const int b = blockIdx.x, tid = threadIdx.x;
    for (int i = tid; i < O_ * H_; i += 128) sW3[i] = W3[i];
    __syncthreads();

    float acc[O_];
#pragma unroll
    for (int o = 0; o < O_; o++) acc[o] = 0.f;
    for (int h = tid; h < H_; h += 128) {
        float s2 = g_S2[b * H_ + h];
#pragma unroll
        for (int o = 0; o < O_; o++) acc[o] += s2 * sW3[o * H_ + h];
    }
#pragma unroll
    for (int off = 16; off; off >>= 1)
#pragma unroll
        for (int o = 0; o < O_; o++)
            acc[o] += __shfl_down_sync(0xffffffffu, acc[o], off);
    if ((tid & 31) == 0)
#pragma unroll
        for (int o = 0; o < O_; o++) part[(tid >> 5) * O_ + o] = acc[o];
    __syncthreads();
    if (tid < O_) {
        float r = 500.0f * b3[tid];
#pragma unroll
        for (int w = 0; w < 4; w++) r += part[w * O_ + tid];
        out[b * O_ + tid] = r;
    }
}

// ---------------- launch ----------------
extern "C" void kernel_launch(void* const* d_in, const int* in_sizes, int n_in,
                              void* d_out, int out_size) {
    const float* x  = (const float*)d_in[0];   // [128, 500, 700]
    const float* W1 = (const float*)d_in[1];   // [512, 700]
    const float* b1 = (const float*)d_in[2];   // [512]
    const float* W2 = (const float*)d_in[3];   // [512, 512]
    const float* b2 = (const float*)d_in[4];   // [512]
    const float* W3 = (const float*)d_in[5];   // [20, 512]
    const float* b3 = (const float*)d_in[6];   // [20]
    float* out = (float*)d_out;                // [128, 20]

    prep_x<<<B_ * T_, 256>>>(x);
    prep_w<<<H_, 256>>>(W1);
    transpose_w2<<<(H_ * H_ + 255) / 256, 256>>>(W2);
    gemm1_mma<<<dim3(H_ / 128, T_), 256>>>(b1);
    scan1_kernel<<<dim3(4, B_), 128>>>();
    layer2_kernel<<<dim3(H_ / 128, B_), 128>>>(b2);
    final_kernel<<<B_, 128>>>(W3, b3, out);
}

// round 6
// speedup vs baseline: 3.7238x; 3.7238x over previous
#include <cuda_runtime.h>
#include <cuda_bf16.h>
#include <cstdint>

#define B_ 128
#define T_ 500
#define D_ 700
#define H_ 512
#define O_ 20
#define K1 704       // GEMM1 K: D padded to 704 (22 stages of 32)
#define K2 512       // GEMM2 K: H (16 stages of 32)
#define RS 80        // smem row stride bytes (64 data + 16 pad -> conflict-free ldmatrix)
#define SBUF (128 * RS)

// ---------------- scratch (static device globals: no allocation allowed) ----------------
__device__ __nv_bfloat16 g_xc[(size_t)T_ * B_ * K1];   // 90 MB   x as bf16 [t][b][k]
__device__ __nv_bfloat16 g_w1[(size_t)H_ * K1];        // W1 bf16 [h][k]
__device__ __nv_bfloat16 g_w2[(size_t)H_ * K2];        // W2 bf16 [g][h] (native layout)
__device__ float         g_cur[(size_t)T_ * B_ * H_];  // 131 MB  cur1 then cur2 [t][b][h]
__device__ __nv_bfloat16 g_s1[(size_t)T_ * B_ * H_];   // 65 MB   s1 dense bf16 [t][b][h]
__device__ float         g_S2[B_ * H_];                // sum over t of s2

// ---------------- helpers ----------------
__device__ __forceinline__ uint32_t smem_u32(const void* p) {
    uint32_t a;
    asm("{ .reg .u64 t; cvta.to.shared.u64 t, %1; cvt.u32.u64 %0, t; }" : "=r"(a) : "l"(p));
    return a;
}
__device__ __forceinline__ void cp16(uint32_t s, const void* g) {
    asm volatile("cp.async.cg.shared.global [%0], [%1], 16;" :: "r"(s), "l"(g));
}
__device__ __forceinline__ void ldsm4(uint32_t& r0, uint32_t& r1, uint32_t& r2,
                                      uint32_t& r3, uint32_t addr) {
    asm volatile("ldmatrix.sync.aligned.m8n8.x4.shared.b16 {%0,%1,%2,%3}, [%4];"
                 : "=r"(r0), "=r"(r1), "=r"(r2), "=r"(r3) : "r"(addr));
}
__device__ __forceinline__ void mma16816(float* c, const uint32_t* a, const uint32_t* b) {
    asm volatile(
        "mma.sync.aligned.m16n8k16.row.col.f32.bf16.bf16.f32 "
        "{%0,%1,%2,%3}, {%4,%5,%6,%7}, {%8,%9}, {%0,%1,%2,%3};"
        : "+f"(c[0]), "+f"(c[1]), "+f"(c[2]), "+f"(c[3])
        : "r"(a[0]), "r"(a[1]), "r"(a[2]), "r"(a[3]), "r"(b[0]), "r"(b[1]));
}

// ---------------- prep: fp32 -> bf16 ----------------
__global__ void prep_x(const float* __restrict__ x) {
    for (int bt = blockIdx.x; bt < B_ * T_; bt += gridDim.x) {
        const int b = bt / T_, t = bt % T_;            // x is [B][T][D]
        const float* xr = x + (size_t)bt * D_;
        __nv_bfloat16* o = g_xc + ((size_t)t * B_ + b) * K1;
        for (int d = threadIdx.x; d < D_; d += 256)
            o[d] = __float2bfloat16(xr[d]);
        if (threadIdx.x < K1 - D_) o[D_ + threadIdx.x] = __float2bfloat16(0.f);
    }
}
__global__ void prep_w1(const float* __restrict__ W1) {
    const int h = blockIdx.x;
    const float* wr = W1 + (size_t)h * D_;
    __nv_bfloat16* o = g_w1 + (size_t)h * K1;
    for (int d = threadIdx.x; d < D_; d += 256)
        o[d] = __float2bfloat16(wr[d]);
    if (threadIdx.x < K1 - D_) o[D_ + threadIdx.x] = __float2bfloat16(0.f);
}
__global__ void prep_w2(const float* __restrict__ W2) {
    int i = blockIdx.x * blockDim.x + threadIdx.x;
    if (i < H_ * H_) g_w2[i] = __float2bfloat16(W2[i]);
}

// ---------------- GEMM template: out[t*B+m][n] = A[t*B+m][:] . Bm[n][:] + bias[n] ------
// grid (4 n-tiles, 500 t), 256 threads. CTA tile M=128 x N=128, K=KK bf16 (KK%32==0).
// 8 warps as 2(m)x4(n), each 64x32 via m16n8k16. cp.async double-buffered K stages of 32.
template <int KK>
__global__ __launch_bounds__(256, 2) void gemm_mma(const __nv_bfloat16* __restrict__ Asrc,
                                                   const __nv_bfloat16* __restrict__ Bsrc,
                                                   const float* __restrict__ bias,
                                                   float* __restrict__ outp) {
    constexpr int NS = KK / 32;
    constexpr int KB2 = KK * 2;
    __shared__ __align__(128) char sA[2 * SBUF];
    __shared__ __align__(128) char sB[2 * SBUF];
    const int tid = threadIdx.x, lane = tid & 31, wid = tid >> 5;
    const int t = blockIdx.y, nbase = blockIdx.x * 128;
    const int wm = wid >> 2, wn = wid & 3;    // warp tile: rows wm*64, cols wn*32

    const char* gA = (const char*)Asrc + (size_t)t * B_ * KB2;
    const char* gB = (const char*)Bsrc + (size_t)nbase * KB2;
    const uint32_t sAu = smem_u32(sA), sBu = smem_u32(sB);

    const int lrow = tid >> 1;
    const int lc = (tid & 1) * 32;            // byte offset of first 16B chunk
    const size_t grow = (size_t)lrow * KB2;

    const int arow = lane & 15;
    const int acol = (lane >> 4) * 16;
    const int brow = (lane & 7) + ((lane & 16) ? 8 : 0);
    const int bcol = (lane & 8) ? 16 : 0;

    float acc[4][4][4];
#pragma unroll
    for (int i = 0; i < 4; i++)
#pragma unroll
        for (int j = 0; j < 4; j++)
#pragma unroll
            for (int q = 0; q < 4; q++) acc[i][j][q] = 0.f;

#define LOADSTAGE(s, buf)                                                       \
    do {                                                                        \
        const char* ga = gA + grow + (s) * 64 + lc;                             \
        const char* gb = gB + grow + (s) * 64 + lc;                             \
        uint32_t da = sAu + (buf) * SBUF + lrow * RS + lc;                      \
        uint32_t db = sBu + (buf) * SBUF + lrow * RS + lc;                      \
        cp16(da, ga); cp16(da + 16, ga + 16);                                   \
        cp16(db, gb); cp16(db + 16, gb + 16);                                   \
    } while (0)

    LOADSTAGE(0, 0);
    asm volatile("cp.async.commit_group;");

    for (int s = 0; s < NS; s++) {
        if (s + 1 < NS) {
            LOADSTAGE(s + 1, (s + 1) & 1);
            asm volatile("cp.async.commit_group;");
            asm volatile("cp.async.wait_group 1;");
        } else {
            asm volatile("cp.async.wait_group 0;");
        }
        __syncthreads();
        const int buf = s & 1;
        const uint32_t abase = sAu + buf * SBUF;
        const uint32_t bbase = sBu + buf * SBUF;
#pragma unroll
        for (int ks = 0; ks < 2; ks++) {
            uint32_t a[4][4], bf[4][2];
#pragma unroll
            for (int i = 0; i < 4; i++)
                ldsm4(a[i][0], a[i][1], a[i][2], a[i][3],
                      abase + (wm * 64 + i * 16 + arow) * RS + acol + ks * 32);
#pragma unroll
            for (int j = 0; j < 2; j++)
                ldsm4(bf[2 * j][0], bf[2 * j][1], bf[2 * j + 1][0], bf[2 * j + 1][1],
                      bbase + (wn * 32 + j * 16 + brow) * RS + bcol + ks * 32);
#pragma unroll
            for (int i = 0; i < 4; i++)
#pragma unroll
                for (int j = 0; j < 4; j++) mma16816(acc[i][j], a[i], bf[j]);
        }
        __syncthreads();
    }

    // epilogue: rows wm*64+i*16 + {lane>>2, +8}, cols wn*32+j*8+(lane&3)*2
    const int r0 = wm * 64 + (lane >> 2);
    const int cb = wn * 32 + (lane & 3) * 2;
#pragma unroll
    for (int j = 0; j < 4; j++) {
        const int col = nbase + cb + j * 8;
        const float2 bl = *(const float2*)(bias + col);
#pragma unroll
        for (int i = 0; i < 4; i++) {
            const int rb = r0 + i * 16;
            float* p0 = outp + ((size_t)(t * B_ + rb)) * H_ + col;
            float* p1 = outp + ((size_t)(t * B_ + rb + 8)) * H_ + col;
            *(float2*)p0 = make_float2(acc[i][j][0] + bl.x, acc[i][j][1] + bl.y);
            *(float2*)p1 = make_float2(acc[i][j][2] + bl.x, acc[i][j][3] + bl.y);
        }
    }
}

// ---------------- scan1: LIF over cur1, writes dense bf16 s1 ----------------
// grid (4 h-quarters, 128 b), 128 threads; thread = one (b,h). No barriers.
__global__ __launch_bounds__(128) void scan1_kernel() {
    const int hq = blockIdx.x, b = blockIdx.y;
    const int tid = threadIdx.x;
    const size_t off = (size_t)b * H_ + hq * 128 + tid;
    const float* cp = g_cur + off;
    __nv_bfloat16* sp = g_s1 + off;
    const __nv_bfloat16 one = __float2bfloat16(1.f);
    const __nv_bfloat16 zero = __float2bfloat16(0.f);
    float v = 0.f;
    for (int t0 = 0; t0 < T_; t0 += 10) {
        float I[10];
#pragma unroll
        for (int u = 0; u < 10; u++)
            I[u] = cp[(size_t)(t0 + u) * (B_ * H_)];
#pragma unroll
        for (int u = 0; u < 10; u++) {
            v += (I[u] - v) * 0.5f;
            bool s = (v >= 1.0f);
            sp[(size_t)(t0 + u) * (B_ * H_)] = s ? one : zero;
            if (s) v = 0.f;
        }
    }
}

// ---------------- scan2: LIF over cur2, accumulates spike counts -> S2 ----------------
__global__ __launch_bounds__(128) void scan2_kernel() {
    const int gq = blockIdx.x, b = blockIdx.y;
    const int tid = threadIdx.x;
    const size_t off = (size_t)b * H_ + gq * 128 + tid;
    const float* cp = g_cur + off;
    float v = 0.f, cnt = 0.f;
    for (int t0 = 0; t0 < T_; t0 += 10) {
        float I[10];
#pragma unroll
        for (int u = 0; u < 10; u++)
            I[u] = cp[(size_t)(t0 + u) * (B_ * H_)];
#pragma unroll
        for (int u = 0; u < 10; u++) {
            v += (I[u] - v) * 0.5f;
            if (v >= 1.0f) { v = 0.f; cnt += 1.f; }
        }
    }
    g_S2[off] = cnt;
}

// ---------------- final: out[b,o] = 500*b3[o] + sum_h S2[b,h] * W3[o,h] ----------------
__global__ void final_kernel(const float* __restrict__ W3, const float* __restrict__ b3,
                             float* __restrict__ out) {
    __shared__ float sW3[O_ * H_];
    __shared__ float part[4 * O_];
    const int b = blockIdx.x, tid = threadIdx.x;
    for (int i = tid; i < O_ * H_; i += 128) sW3[i] = W3[i];
    __syncthreads();

    float acc[O_];
#pragma unroll
    for (int o = 0; o < O_; o++) acc[o] = 0.f;
    for (int h = tid; h < H_; h += 128) {
        float s2 = g_S2[b * H_ + h];
#pragma unroll
        for (int o = 0; o < O_; o++) acc[o] += s2 * sW3[o * H_ + h];
    }
#pragma unroll
    for (int off = 16; off; off >>= 1)
#pragma unroll
        for (int o = 0; o < O_; o++)
            acc[o] += __shfl_down_sync(0xffffffffu, acc[o], off);
    if ((tid & 31) == 0)
#pragma unroll
        for (int o = 0; o < O_; o++) part[(tid >> 5) * O_ + o] = acc[o];
    __syncthreads();
    if (tid < O_) {
        float r = 500.0f * b3[tid];
#pragma unroll
        for (int w = 0; w < 4; w++) r += part[w * O_ + tid];
        out[b * O_ + tid] = r;
    }
}

// ---------------- launch ----------------
extern "C" void kernel_launch(void* const* d_in, const int* in_sizes, int n_in,
                              void* d_out, int out_size) {
    const float* x  = (const float*)d_in[0];   // [128, 500, 700]
    const float* W1 = (const float*)d_in[1];   // [512, 700]
    const float* b1 = (const float*)d_in[2];   // [512]
    const float* W2 = (const float*)d_in[3];   // [512, 512]
    const float* b2 = (const float*)d_in[4];   // [512]
    const float* W3 = (const float*)d_in[5];   // [20, 512]
    const float* b3 = (const float*)d_in[6];   // [20]
    float* out = (float*)d_out;                // [128, 20]

    __nv_bfloat16* xc;  cudaGetSymbolAddress((void**)&xc,  g_xc);
    __nv_bfloat16* w1c; cudaGetSymbolAddress((void**)&w1c, g_w1);
    __nv_bfloat16* w2c; cudaGetSymbolAddress((void**)&w2c, g_w2);
    __nv_bfloat16* s1c; cudaGetSymbolAddress((void**)&s1c, g_s1);
    float* curc;        cudaGetSymbolAddress((void**)&curc, g_cur);

    prep_x<<<2048, 256>>>(x);
    prep_w1<<<H_, 256>>>(W1);
    prep_w2<<<(H_ * H_ + 255) / 256, 256>>>(W2);
    gemm_mma<K1><<<dim3(H_ / 128, T_), 256>>>(xc, w1c, b1, curc);   // cur1
    scan1_kernel<<<dim3(4, B_), 128>>>();                           // s1 (dense bf16)
    gemm_mma<K2><<<dim3(H_ / 128, T_), 256>>>(s1c, w2c, b2, curc);  // cur2 (reuse buffer)
    scan2_kernel<<<dim3(4, B_), 128>>>();                           // S2 counts
    final_kernel<<<B_, 128>>>(W3, b3, out);
}

// round 7
// speedup vs baseline: 4.8129x; 1.2925x over previous
#include <cuda_runtime.h>
#include <cuda_bf16.h>
#include <cstdint>

#define B_ 128
#define T_ 500
#define D_ 700
#define H_ 512
#define O_ 20
#define K1 704       // GEMM1 K: D padded to 704 (22 stages of 32)
#define K2 512       // GEMM2 K: H (16 stages of 32)
#define RS 80        // smem row stride bytes (64 data + 16 pad -> conflict-free ldmatrix)
#define SBUF (128 * RS)
#define STG 4        // cp.async pipeline depth
#define GSMEM (2 * STG * SBUF)   // 81920 bytes dynamic smem
#define ERS 272      // epilogue smem row stride (256 data + 16 -> conflict-free stores)

// ---------------- scratch (static device globals: no allocation allowed) ----------------
__device__ __nv_bfloat16 g_xc[(size_t)T_ * B_ * K1];   // 90 MB   x as bf16 [t][b][k]
__device__ __nv_bfloat16 g_w1[(size_t)H_ * K1];        // W1 bf16 [h][k]
__device__ __nv_bfloat16 g_w2[(size_t)H_ * K2];        // W2 bf16 [g][h] (native layout)
__device__ __nv_bfloat16 g_cur[(size_t)T_ * B_ * H_];  // 65 MB  cur1 then cur2 [t][b][h]
__device__ __nv_bfloat16 g_s1[(size_t)T_ * B_ * H_];   // 65 MB  s1 dense bf16 [t][b][h]
__device__ float         g_S2[B_ * H_];                // sum over t of s2

// ---------------- helpers ----------------
__device__ __forceinline__ uint32_t smem_u32(const void* p) {
    uint32_t a;
    asm("{ .reg .u64 t; cvta.to.shared.u64 t, %1; cvt.u32.u64 %0, t; }" : "=r"(a) : "l"(p));
    return a;
}
__device__ __forceinline__ void cp16(uint32_t s, const void* g) {
    asm volatile("cp.async.cg.shared.global [%0], [%1], 16;" :: "r"(s), "l"(g));
}
__device__ __forceinline__ void ldsm4(uint32_t& r0, uint32_t& r1, uint32_t& r2,
                                      uint32_t& r3, uint32_t addr) {
    asm volatile("ldmatrix.sync.aligned.m8n8.x4.shared.b16 {%0,%1,%2,%3}, [%4];"
                 : "=r"(r0), "=r"(r1), "=r"(r2), "=r"(r3) : "r"(addr));
}
__device__ __forceinline__ void mma16816(float* c, const uint32_t* a, const uint32_t* b) {
    asm volatile(
        "mma.sync.aligned.m16n8k16.row.col.f32.bf16.bf16.f32 "
        "{%0,%1,%2,%3}, {%4,%5,%6,%7}, {%8,%9}, {%0,%1,%2,%3};"
        : "+f"(c[0]), "+f"(c[1]), "+f"(c[2]), "+f"(c[3])
        : "r"(a[0]), "r"(a[1]), "r"(a[2]), "r"(a[3]), "r"(b[0]), "r"(b[1]));
}

// ---------------- prep: fp32 -> bf16 (vectorized: 175 float4 per 700-row) --------------
__global__ __launch_bounds__(192) void prep_x(const float* __restrict__ x) {
    const int bt = blockIdx.x;                         // x is [B][T][D]
    const int b = bt / T_, t = bt % T_;
    const float4* xr = (const float4*)(x + (size_t)bt * D_);
    __nv_bfloat16* o = g_xc + ((size_t)t * B_ + b) * K1;
    const int i = threadIdx.x;
    if (i < 175) {
        float4 v = xr[i];
        __nv_bfloat162 p0 = __floats2bfloat162_rn(v.x, v.y);
        __nv_bfloat162 p1 = __floats2bfloat162_rn(v.z, v.w);
        uint2 u;
        u.x = *(uint32_t*)&p0;
        u.y = *(uint32_t*)&p1;
        *(uint2*)(o + 4 * i) = u;
    } else if (i == 175) {
        *(uint2*)(o + 700) = make_uint2(0u, 0u);       // pad 700..703
    }
}
__global__ void prep_w1(const float* __restrict__ W1) {
    const int h = blockIdx.x;
    const float* wr = W1 + (size_t)h * D_;
    __nv_bfloat16* o = g_w1 + (size_t)h * K1;
    for (int d = threadIdx.x; d < D_; d += 256)
        o[d] = __float2bfloat16(wr[d]);
    if (threadIdx.x < K1 - D_) o[D_ + threadIdx.x] = __float2bfloat16(0.f);
}
__global__ void prep_w2(const float* __restrict__ W2) {
    int i = blockIdx.x * blockDim.x + threadIdx.x;
    if (i < H_ * H_) g_w2[i] = __float2bfloat16(W2[i]);
}

// ---------------- GEMM template: out[t*B+m][n] = bf16(A[t*B+m][:].Bm[n][:] + bias[n]) --
// grid (4 n-tiles, 500 t), 256 threads. CTA tile M=128 x N=128, K=KK bf16 (KK%32==0).
// 8 warps as 2(m)x4(n), each 64x32 via m16n8k16. 4-stage cp.async ring, 1 barrier/stage.
template <int KK>
__global__ __launch_bounds__(256, 2) void gemm_mma(const __nv_bfloat16* __restrict__ Asrc,
                                                   const __nv_bfloat16* __restrict__ Bsrc,
                                                   const float* __restrict__ bias,
                                                   __nv_bfloat16* __restrict__ outp) {
    constexpr int NS = KK / 32;
    constexpr int KB2 = KK * 2;
    extern __shared__ __align__(128) char smem[];
    const int tid = threadIdx.x, lane = tid & 31, wid = tid >> 5;
    const int t = blockIdx.y, nbase = blockIdx.x * 128;
    const int wm = wid >> 2, wn = wid & 3;    // warp tile: rows wm*64, cols wn*32

    const char* gA = (const char*)Asrc + (size_t)t * B_ * KB2;
    const char* gB = (const char*)Bsrc + (size_t)nbase * KB2;
    const uint32_t sAu = smem_u32(smem);
    const uint32_t sBu = sAu + STG * SBUF;

    const int lrow = tid >> 1;
    const int lc = (tid & 1) * 32;            // byte offset of first 16B chunk
    const size_t grow = (size_t)lrow * KB2;

    const int arow = lane & 15;
    const int acol = (lane >> 4) * 16;
    const int brow = (lane & 7) + ((lane & 16) ? 8 : 0);
    const int bcol = (lane & 8) ? 16 : 0;

    float acc[4][4][4];
#pragma unroll
    for (int i = 0; i < 4; i++)
#pragma unroll
        for (int j = 0; j < 4; j++)
#pragma unroll
            for (int q = 0; q < 4; q++) acc[i][j][q] = 0.f;

#define LOADSTAGE(s, buf)                                                       \
    do {                                                                        \
        const char* ga = gA + grow + (s) * 64 + lc;                             \
        const char* gb = gB + grow + (s) * 64 + lc;                             \
        uint32_t da = sAu + (buf) * SBUF + lrow * RS + lc;                      \
        uint32_t db = sBu + (buf) * SBUF + lrow * RS + lc;                      \
        cp16(da, ga); cp16(da + 16, ga + 16);                                   \
        cp16(db, gb); cp16(db + 16, gb + 16);                                   \
    } while (0)

    // prologue: fill STG-1 stages
#pragma unroll
    for (int p = 0; p < STG - 1; p++) {
        LOADSTAGE(p, p);
        asm volatile("cp.async.commit_group;");
    }

    for (int s = 0; s < NS; s++) {
        asm volatile("cp.async.wait_group 2;");   // oldest group (stage s) retired
        __syncthreads();                          // visible to all; buf (s-1)&3 reusable
        if (s + STG - 1 < NS) LOADSTAGE(s + STG - 1, (s + STG - 1) & 3);
        asm volatile("cp.async.commit_group;");   // always commit (may be empty)

        const int buf = s & 3;
        const uint32_t abase = sAu + buf * SBUF;
        const uint32_t bbase = sBu + buf * SBUF;
#pragma unroll
        for (int ks = 0; ks < 2; ks++) {
            uint32_t a[4][4], bf[4][2];
#pragma unroll
            for (int i = 0; i < 4; i++)
                ldsm4(a[i][0], a[i][1], a[i][2], a[i][3],
                      abase + (wm * 64 + i * 16 + arow) * RS + acol + ks * 32);
#pragma unroll
            for (int j = 0; j < 2; j++)
                ldsm4(bf[2 * j][0], bf[2 * j][1], bf[2 * j + 1][0], bf[2 * j + 1][1],
                      bbase + (wn * 32 + j * 16 + brow) * RS + bcol + ks * 32);
#pragma unroll
            for (int i = 0; i < 4; i++)
#pragma unroll
                for (int j = 0; j < 4; j++) mma16816(acc[i][j], a[i], bf[j]);
        }
    }
    __syncthreads();   // all compute done; smem reusable for epilogue staging

    // epilogue: acc -> smem bf16 (row stride ERS, conflict-free), then coalesced copy.
    const int r0 = wm * 64 + (lane >> 2);
    const int cb = wn * 32 + (lane & 3) * 2;
#pragma unroll
    for (int j = 0; j < 4; j++) {
        const int col = nbase + cb + j * 8;
        const float2 bl = *(const float2*)(bias + col);
#pragma unroll
        for (int i = 0; i < 4; i++) {
            const int rb = r0 + i * 16;
            __nv_bfloat162 v0 = __floats2bfloat162_rn(acc[i][j][0] + bl.x,
                                                      acc[i][j][1] + bl.y);
            __nv_bfloat162 v1 = __floats2bfloat162_rn(acc[i][j][2] + bl.x,
                                                      acc[i][j][3] + bl.y);
            *(uint32_t*)(smem + rb * ERS + (cb + j * 8) * 2)       = *(uint32_t*)&v0;
            *(uint32_t*)(smem + (rb + 8) * ERS + (cb + j * 8) * 2) = *(uint32_t*)&v1;
        }
    }
    __syncthreads();
    // 128 rows x 256B -> global; 16B chunks, fully coalesced 256B segments
    char* gOut = (char*)outp + ((size_t)t * B_ * H_ + nbase) * 2;
#pragma unroll
    for (int c = tid; c < 2048; c += 256) {
        const int row = c >> 4, off = (c & 15) * 16;
        uint4 v = *(const uint4*)(smem + row * ERS + off);
        *(uint4*)(gOut + (size_t)row * (H_ * 2) + off) = v;
    }
}

// ---------------- scan1: LIF over cur1 (bf16), writes dense bf16 s1 ----------------
// grid (4 h-quarters, 128 b), 128 threads; thread = one (b,h). No barriers.
__global__ __launch_bounds__(128) void scan1_kernel() {
    const int hq = blockIdx.x, b = blockIdx.y;
    const int tid = threadIdx.x;
    const size_t off = (size_t)b * H_ + hq * 128 + tid;
    const __nv_bfloat16* cp = g_cur + off;
    __nv_bfloat16* sp = g_s1 + off;
    const __nv_bfloat16 one = __float2bfloat16(1.f);
    const __nv_bfloat16 zero = __float2bfloat16(0.f);
    float v = 0.f;
    for (int t0 = 0; t0 < T_; t0 += 10) {
        float I[10];
#pragma unroll
        for (int u = 0; u < 10; u++)
            I[u] = __bfloat162float(cp[(size_t)(t0 + u) * (B_ * H_)]);
#pragma unroll
        for (int u = 0; u < 10; u++) {
            v += (I[u] - v) * 0.5f;
            bool s = (v >= 1.0f);
            sp[(size_t)(t0 + u) * (B_ * H_)] = s ? one : zero;
            if (s) v = 0.f;
        }
    }
}

// ---------------- scan2: LIF over cur2 (bf16), accumulates spike counts -> S2 ----------
__global__ __launch_bounds__(128) void scan2_kernel() {
    const int gq = blockIdx.x, b = blockIdx.y;
    const int tid = threadIdx.x;
    const size_t off = (size_t)b * H_ + gq * 128 + tid;
    const __nv_bfloat16* cp = g_cur + off;
    float v = 0.f, cnt = 0.f;
    for (int t0 = 0; t0 < T_; t0 += 10) {
        float I[10];
#pragma unroll
        for (int u = 0; u < 10; u++)
            I[u] = __bfloat162float(cp[(size_t)(t0 + u) * (B_ * H_)]);
#pragma unroll
        for (int u = 0; u < 10; u++) {
            v += (I[u] - v) * 0.5f;
            if (v >= 1.0f) { v = 0.f; cnt += 1.f; }
        }
    }
    g_S2[off] = cnt;
}

// ---------------- final: out[b,o] = 500*b3[o] + sum_h S2[b,h] * W3[o,h] ----------------
__global__ void final_kernel(const float* __restrict__ W3, const float* __restrict__ b3,
                             float* __restrict__ out) {
    __shared__ float sW3[O_ * H_];
    __shared__ float part[4 * O_];
    const int b = blockIdx.x, tid = threadIdx.x;
    for (int i = tid; i < O_ * H_; i += 128) sW3[i] = W3[i];
    __syncthreads();

    float acc[O_];
#pragma unroll
    for (int o = 0; o < O_; o++) acc[o] = 0.f;
    for (int h = tid; h < H_; h += 128) {
        float s2 = g_S2[b * H_ + h];
#pragma unroll
        for (int o = 0; o < O_; o++) acc[o] += s2 * sW3[o * H_ + h];
    }
#pragma unroll
    for (int off = 16; off; off >>= 1)
#pragma unroll
        for (int o = 0; o < O_; o++)
            acc[o] += __shfl_down_sync(0xffffffffu, acc[o], off);
    if ((tid & 31) == 0)
#pragma unroll
        for (int o = 0; o < O_; o++) part[(tid >> 5) * O_ + o] = acc[o];
    __syncthreads();
    if (tid < O_) {
        float r = 500.0f * b3[tid];
#pragma unroll
        for (int w = 0; w < 4; w++) r += part[w * O_ + tid];
        out[b * O_ + tid] = r;
    }
}

// ---------------- launch ----------------
extern "C" void kernel_launch(void* const* d_in, const int* in_sizes, int n_in,
                              void* d_out, int out_size) {
    const float* x  = (const float*)d_in[0];   // [128, 500, 700]
    const float* W1 = (const float*)d_in[1];   // [512, 700]
    const float* b1 = (const float*)d_in[2];   // [512]
    const float* W2 = (const float*)d_in[3];   // [512, 512]
    const float* b2 = (const float*)d_in[4];   // [512]
    const float* W3 = (const float*)d_in[5];   // [20, 512]
    const float* b3 = (const float*)d_in[6];   // [20]
    float* out = (float*)d_out;                // [128, 20]

    __nv_bfloat16* xc;  cudaGetSymbolAddress((void**)&xc,  g_xc);
    __nv_bfloat16* w1c; cudaGetSymbolAddress((void**)&w1c, g_w1);
    __nv_bfloat16* w2c; cudaGetSymbolAddress((void**)&w2c, g_w2);
    __nv_bfloat16* s1c; cudaGetSymbolAddress((void**)&s1c, g_s1);
    __nv_bfloat16* curc; cudaGetSymbolAddress((void**)&curc, g_cur);

    cudaFuncSetAttribute(gemm_mma<K1>, cudaFuncAttributeMaxDynamicSharedMemorySize, GSMEM);
    cudaFuncSetAttribute(gemm_mma<K2>, cudaFuncAttributeMaxDynamicSharedMemorySize, GSMEM);

    prep_x<<<B_ * T_, 192>>>(x);
    prep_w1<<<H_, 256>>>(W1);
    prep_w2<<<(H_ * H_ + 255) / 256, 256>>>(W2);
    gemm_mma<K1><<<dim3(H_ / 128, T_), 256, GSMEM>>>(xc, w1c, b1, curc);   // cur1
    scan1_kernel<<<dim3(4, B_), 128>>>();                                  // s1 (bf16)
    gemm_mma<K2><<<dim3(H_ / 128, T_), 256, GSMEM>>>(s1c, w2c, b2, curc);  // cur2
    scan2_kernel<<<dim3(4, B_), 128>>>();                                  // S2 counts
    final_kernel<<<B_, 128>>>(W3, b3, out);
}

// round 8
// speedup vs baseline: 4.8853x; 1.0151x over previous
#include <cuda_runtime.h>
#include <cuda_bf16.h>
#include <cstdint>

#define B_ 128
#define T_ 500
#define D_ 700
#define H_ 512
#define O_ 20
#define K1 704       // GEMM1 K: D padded to 704 (11 stages of 64)
#define K2 512       // GEMM2 K: H (8 stages of 64)
#define SBUF 16384   // one stage buffer: 128 rows x 128 B (SW128 swizzled, no pad)
#define STG 3        // cp.async pipeline depth
#define GSMEM (2 * STG * SBUF)   // 98304 bytes dynamic smem
#define ERS 272      // epilogue smem row stride (256 data + 16 -> conflict-free stores)

// ---------------- scratch (static device globals: no allocation allowed) ----------------
__device__ __nv_bfloat16 g_xc[(size_t)T_ * B_ * K1];   // 90 MB   x as bf16 [t][b][k]
__device__ __nv_bfloat16 g_w1[(size_t)H_ * K1];        // W1 bf16 [h][k]
__device__ __nv_bfloat16 g_w2[(size_t)H_ * K2];        // W2 bf16 [g][h] (native layout)
__device__ __nv_bfloat16 g_cur[(size_t)T_ * B_ * H_];  // 65 MB  cur1 then cur2 [t][b][h]
__device__ __nv_bfloat16 g_s1[(size_t)T_ * B_ * H_];   // 65 MB  s1 dense bf16 [t][b][h]
__device__ float         g_S2[B_ * H_];                // sum over t of s2

// ---------------- helpers ----------------
__device__ __forceinline__ uint32_t smem_u32(const void* p) {
    uint32_t a;
    asm("{ .reg .u64 t; cvta.to.shared.u64 t, %1; cvt.u32.u64 %0, t; }" : "=r"(a) : "l"(p));
    return a;
}
__device__ __forceinline__ void cp16(uint32_t s, const void* g) {
    asm volatile("cp.async.cg.shared.global [%0], [%1], 16;" :: "r"(s), "l"(g));
}
__device__ __forceinline__ void ldsm4(uint32_t& r0, uint32_t& r1, uint32_t& r2,
                                      uint32_t& r3, uint32_t addr) {
    asm volatile("ldmatrix.sync.aligned.m8n8.x4.shared.b16 {%0,%1,%2,%3}, [%4];"
                 : "=r"(r0), "=r"(r1), "=r"(r2), "=r"(r3) : "r"(addr));
}
__device__ __forceinline__ void mma16816(float* c, const uint32_t* a, const uint32_t* b) {
    asm volatile(
        "mma.sync.aligned.m16n8k16.row.col.f32.bf16.bf16.f32 "
        "{%0,%1,%2,%3}, {%4,%5,%6,%7}, {%8,%9}, {%0,%1,%2,%3};"
        : "+f"(c[0]), "+f"(c[1]), "+f"(c[2]), "+f"(c[3])
        : "r"(a[0]), "r"(a[1]), "r"(a[2]), "r"(a[3]), "r"(b[0]), "r"(b[1]));
}
__device__ __forceinline__ uint32_t sw128(uint32_t off) {   // SW128: bits[9:7] ^-> [6:4]
    return off ^ ((off >> 3) & 0x70u);
}

// ---------------- prep: fp32 -> bf16 (grid-stride over 16B output chunks) --------------
__global__ __launch_bounds__(256) void prep_x(const float* __restrict__ x) {
    const int total = B_ * T_ * 176;                   // 176 uint2-chunks per row (incl pad)
    for (int c = blockIdx.x * 256 + threadIdx.x; c < total; c += gridDim.x * 256) {
        const int bt = c / 176, i = c - bt * 176;      // x is [B][T][D]
        const int b = bt / T_, t = bt - b * T_;
        __nv_bfloat16* o = g_xc + ((size_t)t * B_ + b) * K1;
        if (i < 175) {
            float4 v = ((const float4*)(x + (size_t)bt * D_))[i];
            __nv_bfloat162 p0 = __floats2bfloat162_rn(v.x, v.y);
            __nv_bfloat162 p1 = __floats2bfloat162_rn(v.z, v.w);
            uint2 u;
            u.x = *(uint32_t*)&p0;
            u.y = *(uint32_t*)&p1;
            *(uint2*)(o + 4 * i) = u;
        } else {
            *(uint2*)(o + 700) = make_uint2(0u, 0u);   // pad 700..703
        }
    }
}
__global__ void prep_w1(const float* __restrict__ W1) {
    const int h = blockIdx.x;
    const float* wr = W1 + (size_t)h * D_;
    __nv_bfloat16* o = g_w1 + (size_t)h * K1;
    for (int d = threadIdx.x; d < D_; d += 256)
        o[d] = __float2bfloat16(wr[d]);
    if (threadIdx.x < K1 - D_) o[D_ + threadIdx.x] = __float2bfloat16(0.f);
}
__global__ void prep_w2(const float* __restrict__ W2) {
    int i = blockIdx.x * blockDim.x + threadIdx.x;
    if (i < H_ * H_) g_w2[i] = __float2bfloat16(W2[i]);
}

// ---------------- GEMM template: out[t*B+m][n] = bf16(A[t*B+m][:].Bm[n][:] + bias[n]) --
// grid (4 n-tiles, 500 t), 256 threads. CTA tile M=128 x N=128, K=KK bf16 (KK%64==0).
// 8 warps as 2(m)x4(n), each 64x32 via m16n8k16. K-stage 64 (SW128 swizzle), 3-stage ring.
template <int KK>
__global__ __launch_bounds__(256, 2) void gemm_mma(const __nv_bfloat16* __restrict__ Asrc,
                                                   const __nv_bfloat16* __restrict__ Bsrc,
                                                   const float* __restrict__ bias,
                                                   __nv_bfloat16* __restrict__ outp) {
    constexpr int NS = KK / 64;
    constexpr int KB2 = KK * 2;
    extern __shared__ __align__(128) char smem[];
    const int tid = threadIdx.x, lane = tid & 31, wid = tid >> 5;
    const int t = blockIdx.y, nbase = blockIdx.x * 128;
    const int wm = wid >> 2, wn = wid & 3;    // warp tile: rows wm*64, cols wn*32

    const char* gA = (const char*)Asrc + (size_t)t * B_ * KB2;
    const char* gB = (const char*)Bsrc + (size_t)nbase * KB2;
    const uint32_t sAu = smem_u32(smem);
    const uint32_t sBu = sAu + STG * SBUF;

    // loader: thread -> row tid>>1, 64B half-row (tid&1), 4 x 16B chunks
    const int lrow = tid >> 1;
    const int lhalf = (tid & 1) * 64;
    const size_t grow = (size_t)lrow * KB2;

    const int arow = lane & 15;
    const int acol = (lane >> 4) * 16;
    const int brow = (lane & 7) + ((lane & 16) ? 8 : 0);
    const int bcol = (lane & 8) ? 16 : 0;

    float acc[4][4][4];
#pragma unroll
    for (int i = 0; i < 4; i++)
#pragma unroll
        for (int j = 0; j < 4; j++)
#pragma unroll
            for (int q = 0; q < 4; q++) acc[i][j][q] = 0.f;

#define LOADSTAGE(s, buf)                                                       \
    do {                                                                        \
        const char* ga = gA + grow + (s) * 128 + lhalf;                         \
        const char* gb = gB + grow + (s) * 128 + lhalf;                         \
        const uint32_t rb = (uint32_t)(lrow * 128 + lhalf);                     \
        _Pragma("unroll")                                                       \
        for (int j = 0; j < 4; j++) {                                           \
            uint32_t sw = sw128(rb + j * 16);                                   \
            cp16(sAu + (buf) * SBUF + sw, ga + j * 16);                         \
            cp16(sBu + (buf) * SBUF + sw, gb + j * 16);                         \
        }                                                                       \
    } while (0)

    // prologue: fill STG-1 = 2 stages
#pragma unroll
    for (int p = 0; p < STG - 1; p++) {
        LOADSTAGE(p, p);
        asm volatile("cp.async.commit_group;");
    }

    int buf = 0, nbuf = STG - 1;
    for (int s = 0; s < NS; s++) {
        asm volatile("cp.async.wait_group 1;");   // stage s resident
        __syncthreads();                          // buf for stage s+2 now reusable
        if (s + STG - 1 < NS) LOADSTAGE(s + STG - 1, nbuf);
        asm volatile("cp.async.commit_group;");   // may be empty on tail

        const uint32_t abase = sAu + buf * SBUF;
        const uint32_t bbase = sBu + buf * SBUF;
#pragma unroll
        for (int ks = 0; ks < 4; ks++) {
            uint32_t a[4][4], bf[4][2];
#pragma unroll
            for (int i = 0; i < 4; i++)
                ldsm4(a[i][0], a[i][1], a[i][2], a[i][3],
                      abase + sw128((wm * 64 + i * 16 + arow) * 128 + ks * 32 + acol));
#pragma unroll
            for (int j = 0; j < 2; j++)
                ldsm4(bf[2 * j][0], bf[2 * j][1], bf[2 * j + 1][0], bf[2 * j + 1][1],
                      bbase + sw128((wn * 32 + j * 16 + brow) * 128 + ks * 32 + bcol));
#pragma unroll
            for (int i = 0; i < 4; i++)
#pragma unroll
                for (int j = 0; j < 4; j++) mma16816(acc[i][j], a[i], bf[j]);
        }
        buf = (buf + 1 == STG) ? 0 : buf + 1;
        nbuf = (nbuf + 1 == STG) ? 0 : nbuf + 1;
    }
    __syncthreads();   // all compute done; smem reusable for epilogue staging

    // epilogue: acc -> smem bf16 (row stride ERS, conflict-free), then coalesced copy.
    const int r0 = wm * 64 + (lane >> 2);
    const int cb = wn * 32 + (lane & 3) * 2;
#pragma unroll
    for (int j = 0; j < 4; j++) {
        const int col = nbase + cb + j * 8;
        const float2 bl = *(const float2*)(bias + col);
#pragma unroll
        for (int i = 0; i < 4; i++) {
            const int rb = r0 + i * 16;
            __nv_bfloat162 v0 = __floats2bfloat162_rn(acc[i][j][0] + bl.x,
                                                      acc[i][j][1] + bl.y);
            __nv_bfloat162 v1 = __floats2bfloat162_rn(acc[i][j][2] + bl.x,
                                                      acc[i][j][3] + bl.y);
            *(uint32_t*)(smem + rb * ERS + (cb + j * 8) * 2)       = *(uint32_t*)&v0;
            *(uint32_t*)(smem + (rb + 8) * ERS + (cb + j * 8) * 2) = *(uint32_t*)&v1;
        }
    }
    __syncthreads();
    // 128 rows x 256B -> global; 16B chunks, fully coalesced 256B segments
    char* gOut = (char*)outp + ((size_t)t * B_ * H_ + nbase) * 2;
#pragma unroll
    for (int c = tid; c < 2048; c += 256) {
        const int row = c >> 4, off = (c & 15) * 16;
        uint4 v = *(const uint4*)(smem + row * ERS + off);
        *(uint4*)(gOut + (size_t)row * (H_ * 2) + off) = v;
    }
}

// ---------------- scan1: LIF over cur1 (bf16x2), writes dense bf16 s1 ----------------
// grid (2 h-halves, 128 b), 128 threads; thread = one (b, h-pair). No barriers.
__global__ __launch_bounds__(128) void scan1_kernel() {
    const int q = blockIdx.x, b = blockIdx.y;
    const int tid = threadIdx.x;
    const size_t off2 = (size_t)b * (H_ / 2) + q * 128 + tid;   // bf162 index
    const __nv_bfloat162* cp = (const __nv_bfloat162*)g_cur + off2;
    __nv_bfloat162* sp = (__nv_bfloat162*)g_s1 + off2;
    const int stride = B_ * H_ / 2;
    float v0 = 0.f, v1 = 0.f;
    for (int t0 = 0; t0 < T_; t0 += 10) {
        __nv_bfloat162 I[10];
#pragma unroll
        for (int u = 0; u < 10; u++)
            I[u] = cp[(size_t)(t0 + u) * stride];
#pragma unroll
        for (int u = 0; u < 10; u++) {
            float2 f = __bfloat1622float2(I[u]);
            v0 += (f.x - v0) * 0.5f;
            v1 += (f.y - v1) * 0.5f;
            bool s0 = (v0 >= 1.0f), s1v = (v1 >= 1.0f);
            sp[(size_t)(t0 + u) * stride] =
                __floats2bfloat162_rn(s0 ? 1.f : 0.f, s1v ? 1.f : 0.f);
            if (s0) v0 = 0.f;
            if (s1v) v1 = 0.f;
        }
    }
}

// ---------------- scan2: LIF over cur2 (bf16x2), accumulates spike counts -> S2 --------
__global__ __launch_bounds__(128) void scan2_kernel() {
    const int q = blockIdx.x, b = blockIdx.y;
    const int tid = threadIdx.x;
    const size_t off2 = (size_t)b * (H_ / 2) + q * 128 + tid;
    const __nv_bfloat162* cp = (const __nv_bfloat162*)g_cur + off2;
    const int stride = B_ * H_ / 2;
    float v0 = 0.f, v1 = 0.f, c0 = 0.f, c1 = 0.f;
    for (int t0 = 0; t0 < T_; t0 += 10) {
        __nv_bfloat162 I[10];
#pragma unroll
        for (int u = 0; u < 10; u++)
            I[u] = cp[(size_t)(t0 + u) * stride];
#pragma unroll
        for (int u = 0; u < 10; u++) {
            float2 f = __bfloat1622float2(I[u]);
            v0 += (f.x - v0) * 0.5f;
            v1 += (f.y - v1) * 0.5f;
            if (v0 >= 1.0f) { v0 = 0.f; c0 += 1.f; }
            if (v1 >= 1.0f) { v1 = 0.f; c1 += 1.f; }
        }
    }
    float2* o = (float2*)(g_S2 + 2 * off2);
    *o = make_float2(c0, c1);
}

// ---------------- final: out[b,o] = 500*b3[o] + sum_h S2[b,h] * W3[o,h] ----------------
__global__ void final_kernel(const float* __restrict__ W3, const float* __restrict__ b3,
                             float* __restrict__ out) {
    __shared__ float sW3[O_ * H_];
    __shared__ float part[4 * O_];
    const int b = blockIdx.x, tid = threadIdx.x;
    for (int i = tid; i < O_ * H_; i += 128) sW3[i] = W3[i];
    __syncthreads();

    float acc[O_];
#pragma unroll
    for (int o = 0; o < O_; o++) acc[o] = 0.f;
    for (int h = tid; h < H_; h += 128) {
        float s2 = g_S2[b * H_ + h];
#pragma unroll
        for (int o = 0; o < O_; o++) acc[o] += s2 * sW3[o * H_ + h];
    }
#pragma unroll
    for (int off = 16; off; off >>= 1)
#pragma unroll
        for (int o = 0; o < O_; o++)
            acc[o] += __shfl_down_sync(0xffffffffu, acc[o], off);
    if ((tid & 31) == 0)
#pragma unroll
        for (int o = 0; o < O_; o++) part[(tid >> 5) * O_ + o] = acc[o];
    __syncthreads();
    if (tid < O_) {
        float r = 500.0f * b3[tid];
#pragma unroll
        for (int w = 0; w < 4; w++) r += part[w * O_ + tid];
        out[b * O_ + tid] = r;
    }
}

// ---------------- launch ----------------
extern "C" void kernel_launch(void* const* d_in, const int* in_sizes, int n_in,
                              void* d_out, int out_size) {
    const float* x  = (const float*)d_in[0];   // [128, 500, 700]
    const float* W1 = (const float*)d_in[1];   // [512, 700]
    const float* b1 = (const float*)d_in[2];   // [512]
    const float* W2 = (const float*)d_in[3];   // [512, 512]
    const float* b2 = (const float*)d_in[4];   // [512]
    const float* W3 = (const float*)d_in[5];   // [20, 512]
    const float* b3 = (const float*)d_in[6];   // [20]
    float* out = (float*)d_out;                // [128, 20]

    __nv_bfloat16* xc;  cudaGetSymbolAddress((void**)&xc,  g_xc);
    __nv_bfloat16* w1c; cudaGetSymbolAddress((void**)&w1c, g_w1);
    __nv_bfloat16* w2c; cudaGetSymbolAddress((void**)&w2c, g_w2);
    __nv_bfloat16* s1c; cudaGetSymbolAddress((void**)&s1c, g_s1);
    __nv_bfloat16* curc; cudaGetSymbolAddress((void**)&curc, g_cur);

    cudaFuncSetAttribute(gemm_mma<K1>, cudaFuncAttributeMaxDynamicSharedMemorySize, GSMEM);
    cudaFuncSetAttribute(gemm_mma<K2>, cudaFuncAttributeMaxDynamicSharedMemorySize, GSMEM);

    prep_x<<<8192, 256>>>(x);
    prep_w1<<<H_, 256>>>(W1);
    prep_w2<<<(H_ * H_ + 255) / 256, 256>>>(W2);
    gemm_mma<K1><<<dim3(H_ / 128, T_), 256, GSMEM>>>(xc, w1c, b1, curc);   // cur1
    scan1_kernel<<<dim3(2, B_), 128>>>();                                  // s1 (bf16)
    gemm_mma<K2><<<dim3(H_ / 128, T_), 256, GSMEM>>>(s1c, w2c, b2, curc);  // cur2
    scan2_kernel<<<dim3(2, B_), 128>>>();                                  // S2 counts
    final_kernel<<<B_, 128>>>(W3, b3, out);
}